// round 13
// baseline (speedup 1.0000x reference)
#include <cuda_runtime.h>
#include <cuda.h>
#include <cuda_fp16.h>
#include <math.h>

#define Bn   16
#define Ln   512
#define Cn   38
#define Dn   512
#define Hn   8
#define En   64
#define DFFn 2048
#define NLn  3
#define DRESn 128
#define Mn   (Bn*Ln)     /* 8192 */
#define BHn  (Bn*Hn)     /* 128  */

// ---------------- scratch (static device memory) ----------------
__device__ float  g_h   [Mn*Dn];
__device__ float  g_x1  [Mn*Dn];
__device__ float  g_tmp [Mn*Dn];
__device__ __align__(16) __half g_h16  [Mn*Dn];
__device__ __align__(16) __half g_x1h  [Mn*Dn];
__device__ __align__(16) __half g_enc16[Mn*Dn];
__device__ __align__(16) __half g_qkv  [Mn*1536];
__device__ __align__(16) __half g_attnv[Mn*Dn];
__device__ __align__(16) __half g_ff1  [Mn*DFFn];
__device__ __align__(16) __half g_xcat [Mn*128];
__device__ __align__(16) __half g_wt   [9830400];     // transposed weights (half)
__device__ float  g_bqkv[NLn*1536];

#define WQKV(l) ((size_t)(l) * 786432)                 /* fused [1536][512] per layer */
#define WTO 2359296
#define WT1 3145728
#define WT2 6291456
#define WTP 9437184
#define WTF 9699328
#define KTF 9764864

// ================= helpers =================
__device__ __forceinline__ unsigned smem_u32(const void* p) {
    unsigned a;
    asm("{ .reg .u64 t; cvta.to.shared.u64 t, %1; cvt.u32.u64 %0, t; }"
        : "=r"(a) : "l"(p));
    return a;
}
__device__ __forceinline__ void mma16(float* c, const unsigned* a, const unsigned* b) {
    asm volatile("mma.sync.aligned.m16n8k16.row.col.f32.f16.f16.f32 "
        "{%0,%1,%2,%3}, {%4,%5,%6,%7}, {%8,%9}, {%0,%1,%2,%3};"
        : "+f"(c[0]), "+f"(c[1]), "+f"(c[2]), "+f"(c[3])
        : "r"(a[0]), "r"(a[1]), "r"(a[2]), "r"(a[3]), "r"(b[0]), "r"(b[1]));
}
__device__ __forceinline__ void ldsm4(unsigned* r, unsigned addr) {
    asm volatile("ldmatrix.sync.aligned.m8n8.x4.shared.b16 {%0,%1,%2,%3}, [%4];"
        : "=r"(r[0]), "=r"(r[1]), "=r"(r[2]), "=r"(r[3]) : "r"(addr));
}
__device__ __forceinline__ void ldsm4t(unsigned* r, unsigned addr) {
    asm volatile("ldmatrix.sync.aligned.m8n8.x4.trans.shared.b16 {%0,%1,%2,%3}, [%4];"
        : "=r"(r[0]), "=r"(r[1]), "=r"(r[2]), "=r"(r[3]) : "r"(addr));
}
__device__ __forceinline__ unsigned h2u(__half2 v) { return *(unsigned*)&v; }
#define CP16(sa, gp) \
    asm volatile("cp.async.cg.shared.global [%0], [%1], 16;" :: "r"(sa), "l"(gp))
#define CPCOMMIT() asm volatile("cp.async.commit_group;" ::: "memory")
#define CPWAIT(n)  asm volatile("cp.async.wait_group %0;" :: "n"(n) : "memory")

// == fp16 tensor-core GEMM (3-stage pipeline, K-chunk 64, templated trips) ===
// NCT > 0: compile-time chunk count (fully unrolled). NCT == 0: runtime (K/64).
// resid: optional fp32 [M x ldc] added in epilogue (residual fusion).
template<int NT, int NCT>
__global__ __launch_bounds__(256, 2)
void gemm_mma(const __half* __restrict__ A, int lda,
              const __half* __restrict__ BT, int ldb,
              const float* __restrict__ bias,
              const float* __restrict__ resid,
              float* __restrict__ C, __half* __restrict__ C16, int ldc,
              int K, int do_gelu)
{
    constexpr int WC  = 4;
    constexpr int WM  = 64;
    constexpr int MT  = WM / 16;
    constexpr int RS  = 72;                   // 64 data halves + 8 pad
    constexpr int STG = (128 + NT) * RS;      // halves per stage

    extern __shared__ __align__(16) char dsm[];
    __half* sm = (__half*)dsm;
    const int tid = threadIdx.x, w = tid >> 5, lane = tid & 31;
    const int m0 = blockIdx.y * 128, n0 = blockIdx.x * NT;
    const int g = lane >> 3, lr = lane & 7;

    auto load_stage = [&](int kc, int st) {
        __half* As = sm + st * STG;
        __half* Bs = As + 128 * RS;
        const __half* Ap = A + (size_t)m0 * lda + kc * 64;
#pragma unroll
        for (int i = 0; i < 4; i++) {
            int fi = tid + i * 256, row = fi >> 3, seg = fi & 7;
            CP16(smem_u32(As + row * RS + seg * 8), Ap + (size_t)row * lda + seg * 8);
        }
        const __half* Bp = BT + (size_t)n0 * ldb + kc * 64;
#pragma unroll
        for (int i = 0; i < NT / 32; i++) {
            int fi = tid + i * 256, row = fi >> 3, seg = fi & 7;
            CP16(smem_u32(Bs + row * RS + seg * 8), Bp + (size_t)row * ldb + seg * 8);
        }
    };

    float acc[MT][4][4];
#pragma unroll
    for (int mt = 0; mt < MT; mt++)
#pragma unroll
        for (int nt = 0; nt < 4; nt++)
#pragma unroll
            for (int j = 0; j < 4; j++) acc[mt][nt][j] = 0.f;

    const int wm0 = (w / WC) * WM, wn0 = (w % WC) * 32;
    const int r = lane >> 2, cl = lane & 3;
    const unsigned aLane = ((g & 1) * 8 + lr) * RS + (g >> 1) * 8;
    const unsigned bLane = ((g >> 1) * 8 + lr) * RS + (g & 1) * 8;

    auto compute = [&](int st) {
        __half* As = sm + st * STG;
        __half* Bs = As + 128 * RS;
        unsigned aBase = smem_u32(As) + 2u * (wm0 * RS + aLane);
        unsigned bBase = smem_u32(Bs) + 2u * (wn0 * RS + bLane);
#pragma unroll
        for (int ks = 0; ks < 4; ks++) {          // four k16 steps per 64-chunk
            const unsigned koff = ks * 32;
            unsigned a[MT][4], b[4][2];
#pragma unroll
            for (int mt = 0; mt < MT; mt++)
                ldsm4(a[mt], aBase + mt * (16 * RS * 2) + koff);
#pragma unroll
            for (int p = 0; p < 2; p++) {
                unsigned t[4];
                ldsm4(t, bBase + p * (16 * RS * 2) + koff);
                b[2 * p][0] = t[0]; b[2 * p][1] = t[1];
                b[2 * p + 1][0] = t[2]; b[2 * p + 1][1] = t[3];
            }
#pragma unroll
            for (int mt = 0; mt < MT; mt++)
#pragma unroll
                for (int nt = 0; nt < 4; nt++)
                    mma16(acc[mt][nt], a[mt], b[nt]);
        }
    };

    auto step = [&](int c, int NCloc) {
        if (c + 1 < NCloc) { CPWAIT(1); }      // chunk c landed; c+1 may fly
        else              { CPWAIT(0); }       // final chunk fully landed
        __syncthreads();
        compute(c % 3);
        if (c + 2 < NCloc) {
            load_stage(c + 2, (c + 2) % 3);
            CPCOMMIT();
        }
    };

    load_stage(0, 0); CPCOMMIT();
    load_stage(1, 1); CPCOMMIT();

    if constexpr (NCT > 0) {
#pragma unroll
        for (int c = 0; c < NCT; c++) step(c, NCT);
    } else {
        const int NC = K >> 6;
#pragma unroll 4
        for (int c = 0; c < NC; c++) step(c, NC);
    }

#pragma unroll
    for (int mt = 0; mt < MT; mt++) {
#pragma unroll
        for (int nt = 0; nt < 4; nt++) {
            int row = m0 + wm0 + mt * 16 + r;
            int col = n0 + wn0 + nt * 8 + cl * 2;
            float bs0 = bias ? bias[col] : 0.f;
            float bs1 = bias ? bias[col + 1] : 0.f;
            float v0 = acc[mt][nt][0] + bs0;
            float v1 = acc[mt][nt][1] + bs1;
            float v2 = acc[mt][nt][2] + bs0;
            float v3 = acc[mt][nt][3] + bs1;
            if (do_gelu) {
                v0 = 0.5f * v0 * (1.0f + erff(v0 * 0.70710678118654752f));
                v1 = 0.5f * v1 * (1.0f + erff(v1 * 0.70710678118654752f));
                v2 = 0.5f * v2 * (1.0f + erff(v2 * 0.70710678118654752f));
                v3 = 0.5f * v3 * (1.0f + erff(v3 * 0.70710678118654752f));
            }
            if (resid) {
                const float* r0 = resid + (size_t)row * ldc + col;
                const float* r1 = r0 + (size_t)8 * ldc;
                v0 += r0[0]; v1 += r0[1];
                v2 += r1[0]; v3 += r1[1];
            }
            if (C) {
                float* p0 = C + (size_t)row * ldc + col;
                float* p1 = p0 + (size_t)8 * ldc;
                p0[0] = v0; p0[1] = v1;
                p1[0] = v2; p1[1] = v3;
            }
            if (C16) {
                *(__half2*)(C16 + (size_t)row * ldc + col) = __floats2half2_rn(v0, v1);
                *(__half2*)(C16 + (size_t)(row + 8) * ldc + col) = __floats2half2_rn(v2, v3);
            }
        }
    }
}

// ================= flash attention: scores + softmax + P.V ==================
#define FL_RSQ 72
#define FL_RSK 72
#define FL_RSV 72
#define FL_KOFF (32*FL_RSQ)                    /* halves */
#define FL_VOFF (FL_KOFF + 512*FL_RSK)
#define FL_REDB ((FL_VOFF + 512*FL_RSV)*2)     /* bytes  */
#define FL_SMEM (FL_REDB + 2048 + 16)

__global__ __launch_bounds__(256, 1)
void flash_attn(const __half* __restrict__ qkv,
                __half* __restrict__ attnv)
{
    extern __shared__ __align__(16) char dsm[];
    __half* Qs = (__half*)dsm;
    __half* Ks = Qs + FL_KOFF;
    __half* Vs = Qs + FL_VOFF;
    float* red  = (float*)(dsm + FL_REDB);
    float* red2 = red + 256;

    const int tid = threadIdx.x, w = tid >> 5, lane = tid & 31;
    const int r = lane >> 2, cl = lane & 3;
    const int g = lane >> 3, lr = lane & 7;
    const int z = blockIdx.x;
    const int m0 = blockIdx.y * 32;
    const int b = z >> 3, hh = z & 7;
    const size_t qbase = ((size_t)b * Ln) * 1536 + (size_t)hh * 64;

    {
        int row = tid >> 3, seg = tid & 7;
        *(uint4*)(Qs + row * FL_RSQ + seg * 8) =
            *(const uint4*)(qkv + qbase + (size_t)(m0 + row) * 1536 + seg * 8);
    }
#pragma unroll 4
    for (int i = 0; i < 16; i++) {
        int idx = tid + i * 256, row = idx >> 3, seg = idx & 7;
        const __half* src = qkv + qbase + 512 + (size_t)row * 1536 + seg * 8;
        *(uint4*)(Ks + row * FL_RSK + seg * 8) = *(const uint4*)src;
        *(uint4*)(Vs + row * FL_RSV + seg * 8) = *(const uint4*)(src + 512);
    }
    __syncthreads();

    const int wn0 = w * 64;
    float acc[2][8][4];
#pragma unroll
    for (int mt = 0; mt < 2; mt++)
#pragma unroll
        for (int nt = 0; nt < 8; nt++)
#pragma unroll
            for (int j = 0; j < 4; j++) acc[mt][nt][j] = 0.f;

    const unsigned aBase = smem_u32(Qs) + 2u * (((g & 1) * 8 + lr) * FL_RSQ + (g >> 1) * 8);
    const unsigned bBase = smem_u32(Ks) + 2u * ((wn0 + (g >> 1) * 8 + lr) * FL_RSK + (g & 1) * 8);
#pragma unroll
    for (int ks = 0; ks < 4; ks++) {
        const unsigned koff = ks * 32;
        unsigned a[2][4], b[8][2];
#pragma unroll
        for (int mt = 0; mt < 2; mt++)
            ldsm4(a[mt], aBase + mt * (16 * FL_RSQ * 2) + koff);
#pragma unroll
        for (int p = 0; p < 4; p++) {
            unsigned t[4];
            ldsm4(t, bBase + p * (16 * FL_RSK * 2) + koff);
            b[2 * p][0] = t[0]; b[2 * p][1] = t[1];
            b[2 * p + 1][0] = t[2]; b[2 * p + 1][1] = t[3];
        }
#pragma unroll
        for (int mt = 0; mt < 2; mt++)
#pragma unroll
            for (int nt = 0; nt < 8; nt++)
                mma16(acc[mt][nt], a[mt], b[nt]);
    }

    float M[4], inv[4];
#pragma unroll
    for (int rs = 0; rs < 4; rs++) {
        int mt = rs >> 1, jb = (rs & 1) * 2;
        float mx = -1e30f;
#pragma unroll
        for (int nt = 0; nt < 8; nt++)
            mx = fmaxf(mx, fmaxf(acc[mt][nt][jb], acc[mt][nt][jb + 1]));
        mx = fmaxf(mx, __shfl_xor_sync(0xFFFFFFFFu, mx, 1));
        mx = fmaxf(mx, __shfl_xor_sync(0xFFFFFFFFu, mx, 2));
        if (cl == 0) red[w * 32 + mt * 16 + r + (rs & 1) * 8] = mx;
    }
    __syncthreads();
#pragma unroll
    for (int rs = 0; rs < 4; rs++) {
        int row = (rs >> 1) * 16 + r + (rs & 1) * 8;
        float mx = -1e30f;
#pragma unroll
        for (int w2 = 0; w2 < 8; w2++) mx = fmaxf(mx, red[w2 * 32 + row]);
        M[rs] = mx;
    }
#pragma unroll
    for (int rs = 0; rs < 4; rs++) {
        int mt = rs >> 1, jb = (rs & 1) * 2;
        float s = 0.f;
#pragma unroll
        for (int nt = 0; nt < 8; nt++) {
            float e0 = __expf((acc[mt][nt][jb]     - M[rs]) * 0.125f);
            float e1 = __expf((acc[mt][nt][jb + 1] - M[rs]) * 0.125f);
            acc[mt][nt][jb] = e0; acc[mt][nt][jb + 1] = e1;
            s += e0 + e1;
        }
        s += __shfl_xor_sync(0xFFFFFFFFu, s, 1);
        s += __shfl_xor_sync(0xFFFFFFFFu, s, 2);
        if (cl == 0) red2[w * 32 + mt * 16 + r + (rs & 1) * 8] = s;
    }
    __syncthreads();
#pragma unroll
    for (int rs = 0; rs < 4; rs++) {
        int row = (rs >> 1) * 16 + r + (rs & 1) * 8;
        float s = 0.f;
#pragma unroll
        for (int w2 = 0; w2 < 8; w2++) s += red2[w2 * 32 + row];
        inv[rs] = 1.0f / s;
    }

    float o[2][8][4];
#pragma unroll
    for (int mt = 0; mt < 2; mt++)
#pragma unroll
        for (int nt = 0; nt < 8; nt++)
#pragma unroll
            for (int j = 0; j < 4; j++) o[mt][nt][j] = 0.f;

    const unsigned vBase = smem_u32(Vs) + 2u * ((wn0 + (g & 1) * 8 + lr) * FL_RSV + (g >> 1) * 8);
#pragma unroll
    for (int t = 0; t < 4; t++) {
        unsigned a[2][4], b[8][2];
#pragma unroll
        for (int mt = 0; mt < 2; mt++) {
            a[mt][0] = h2u(__floats2half2_rn(acc[mt][2*t][0]   * inv[2*mt],     acc[mt][2*t][1]   * inv[2*mt]));
            a[mt][1] = h2u(__floats2half2_rn(acc[mt][2*t][2]   * inv[2*mt + 1], acc[mt][2*t][3]   * inv[2*mt + 1]));
            a[mt][2] = h2u(__floats2half2_rn(acc[mt][2*t+1][0] * inv[2*mt],     acc[mt][2*t+1][1] * inv[2*mt]));
            a[mt][3] = h2u(__floats2half2_rn(acc[mt][2*t+1][2] * inv[2*mt + 1], acc[mt][2*t+1][3] * inv[2*mt + 1]));
        }
#pragma unroll
        for (int p = 0; p < 4; p++) {
            unsigned tb[4];
            ldsm4t(tb, vBase + t * (16 * FL_RSV * 2) + p * 32);
            b[2 * p][0] = tb[0]; b[2 * p][1] = tb[1];
            b[2 * p + 1][0] = tb[2]; b[2 * p + 1][1] = tb[3];
        }
#pragma unroll
        for (int mt = 0; mt < 2; mt++)
#pragma unroll
            for (int nt = 0; nt < 8; nt++)
                mma16(o[mt][nt], a[mt], b[nt]);
    }

    float* part = (float*)(dsm + FL_KOFF * 2);
#pragma unroll
    for (int mt = 0; mt < 2; mt++)
#pragma unroll
        for (int nt = 0; nt < 8; nt++) {
            int row = mt * 16 + r, col = nt * 8 + cl * 2;
            float* p = part + w * 2112 + row * 66 + col;
            p[0] = o[mt][nt][0]; p[1] = o[mt][nt][1];
            p[8 * 66] = o[mt][nt][2]; p[8 * 66 + 1] = o[mt][nt][3];
        }
    __syncthreads();

    {
        int orow = tid >> 3, c0 = (tid & 7) * 8;
        float s[8];
#pragma unroll
        for (int c = 0; c < 8; c++) s[c] = 0.f;
#pragma unroll
        for (int w2 = 0; w2 < 8; w2++) {
            const float* p = part + w2 * 2112 + orow * 66 + c0;
#pragma unroll
            for (int c = 0; c < 8; c++) s[c] += p[c];
        }
        __align__(16) __half2 hb[4];
#pragma unroll
        for (int c = 0; c < 4; c++) hb[c] = __floats2half2_rn(s[2 * c], s[2 * c + 1]);
        *(uint4*)(attnv + ((size_t)b * Ln + m0 + orow) * Dn + hh * 64 + c0) = *(uint4*)hb;
    }
}

// ================= batched weight transpose (ALL weights, one launch) =======
__global__ void transpose_all(const float* __restrict__ Wq, const float* __restrict__ Wk,
                              const float* __restrict__ Wv, const float* __restrict__ Wo,
                              const float* __restrict__ W1, const float* __restrict__ W2,
                              const float* __restrict__ Wproj, const float* __restrict__ Wfea,
                              __half* __restrict__ wt)
{
    int bid = blockIdx.x;
    const float* in; __half* out; int K, N, bx, by;
    if (bid < 9216) {
        int l = bid / 3072, rr = bid - l * 3072;
        size_t o512 = (size_t)l * 262144, o1 = (size_t)l * 1048576;
        if (rr < 1024) {
            int m = rr >> 8, idx = rr & 255;
            K = 512; N = 512; bx = idx & 15; by = idx >> 4;
            if (m == 0)      { in = Wq + o512; out = wt + WQKV(l); }
            else if (m == 1) { in = Wk + o512; out = wt + WQKV(l) + 262144; }
            else if (m == 2) { in = Wv + o512; out = wt + WQKV(l) + 524288; }
            else             { in = Wo + o512; out = wt + WTO + o512; }
        } else if (rr < 2048) {
            int idx = rr - 1024;
            K = 512; N = 2048; bx = idx & 63; by = idx >> 6;
            in = W1 + o1; out = wt + WT1 + o1;
        } else {
            int idx = rr - 2048;
            K = 2048; N = 512; bx = idx & 15; by = idx >> 4;
            in = W2 + o1; out = wt + WT2 + o1;
        }
    } else if (bid < 9472) {
        int idx = bid - 9216;
        K = 512; N = 512; bx = idx & 15; by = idx >> 4;
        in = Wproj; out = wt + WTP;
    } else {
        int idx = bid - 9472;
        K = 128; N = 512; bx = idx & 15; by = idx >> 4;
        in = Wfea; out = wt + WTF;
    }
    __shared__ float t[32][33];
    int k0 = by * 32, n0 = bx * 32;
    int tx = threadIdx.x, ty = threadIdx.y;
#pragma unroll
    for (int rr2 = 0; rr2 < 4; rr2++)
        t[ty + rr2 * 8][tx] = in[(size_t)(k0 + ty + rr2 * 8) * N + n0 + tx];
    __syncthreads();
#pragma unroll
    for (int rr2 = 0; rr2 < 4; rr2++)
        out[(size_t)(n0 + ty + rr2 * 8) * K + k0 + tx] = __float2half(t[tx][ty + rr2 * 8]);
}

// ================= combined small packs: ktf | bqkv | xcat ==================
__global__ void pack_misc(const float* __restrict__ kern,
                          const float* __restrict__ bq, const float* __restrict__ bk,
                          const float* __restrict__ bv,
                          const float* __restrict__ x,
                          __half* __restrict__ kt, float* __restrict__ bdst,
                          __half* __restrict__ xc)
{
    int bid = blockIdx.x, tidx = threadIdx.x;
    if (bid < 512) {
        int d = bid;
        kt[(size_t)d * 128 + tidx] =
            __float2half((tidx < Cn * 3) ? kern[(size_t)d * (Cn * 3) + tidx] : 0.f);
    } else if (bid < 524) {
        int j = bid - 512;
        int l = j >> 2, i = (j & 3) * 128 + tidx;
        bdst[l * 1536 + i]        = bq[l * 512 + i];
        bdst[l * 1536 + 512 + i]  = bk[l * 512 + i];
        bdst[l * 1536 + 1024 + i] = bv[l * 512 + i];
    } else {
        int bl = bid - 524;
        int b = bl >> 9, l = bl & 511;
        float val = 0.f;
        if (tidx < Cn * 3) {
            int c = tidx / 3, t = tidx - c * 3;
            int ls = (l - 1 + t + Ln) & (Ln - 1);
            val = x[((size_t)b * Ln + ls) * Cn + c];
        }
        xc[(size_t)bl * 128 + tidx] = __float2half(val);
    }
}

// ===== layernorm (single input, 2 rows per CTA, 128 thr x float4 each) =====
__global__ void add_ln512(const float* __restrict__ a,
                          const float* __restrict__ g, const float* __restrict__ be,
                          float* __restrict__ o, __half* __restrict__ o16,
                          float* __restrict__ res) {
    int row = blockIdx.x * 2 + threadIdx.y, t = threadIdx.x;   // (128,2)
    size_t base = (size_t)row * Dn;
    float4 v = *(const float4*)(a + base + t * 4);
    float s = v.x + v.y + v.z + v.w;
#pragma unroll
    for (int oo = 16; oo > 0; oo >>= 1) s += __shfl_xor_sync(0xFFFFFFFFu, s, oo);
    __shared__ float s1[2][4], s2[2][4];
    if ((t & 31) == 0) s1[threadIdx.y][t >> 5] = s;
    __syncthreads();
    float mean = (s1[threadIdx.y][0] + s1[threadIdx.y][1] +
                  s1[threadIdx.y][2] + s1[threadIdx.y][3]) * (1.0f / Dn);
    float d0 = v.x - mean, d1 = v.y - mean, d2 = v.z - mean, d3 = v.w - mean;
    float q2 = d0 * d0 + d1 * d1 + d2 * d2 + d3 * d3;
#pragma unroll
    for (int oo = 16; oo > 0; oo >>= 1) q2 += __shfl_xor_sync(0xFFFFFFFFu, q2, oo);
    if ((t & 31) == 0) s2[threadIdx.y][t >> 5] = q2;
    __syncthreads();
    float var = (s2[threadIdx.y][0] + s2[threadIdx.y][1] +
                 s2[threadIdx.y][2] + s2[threadIdx.y][3]) * (1.0f / Dn);
    float rr = rsqrtf(var + 1e-5f);
    float4 gg = *(const float4*)(g + t * 4);
    float4 bb = *(const float4*)(be + t * 4);
    float o0 = d0 * rr * gg.x + bb.x;
    float o1 = d1 * rr * gg.y + bb.y;
    float o2 = d2 * rr * gg.z + bb.z;
    float o3 = d3 * rr * gg.w + bb.w;
    if (o) {
        float4 ov = {o0, o1, o2, o3};
        *(float4*)(o + base + t * 4) = ov;
    }
    if (o16) {
        *(__half2*)(o16 + base + t * 4)     = __floats2half2_rn(o0, o1);
        *(__half2*)(o16 + base + t * 4 + 2) = __floats2half2_rn(o2, o3);
    }
    if (res && t < 96) {
        float4 rv = {o0, o1, o2, o3};
        *(float4*)(res + (size_t)row * 384 + t * 4) = rv;
    }
}

// ================= launcher =================
extern "C" void kernel_launch(void* const* d_in, const int* in_sizes, int n_in,
                              void* d_out, int out_size)
{
    const float* x     = (const float*)d_in[0];
    const float* embk  = (const float*)d_in[1];
    const float* Wq    = (const float*)d_in[2];
    const float* bq    = (const float*)d_in[3];
    const float* Wk    = (const float*)d_in[4];
    const float* bk    = (const float*)d_in[5];
    const float* Wv    = (const float*)d_in[6];
    const float* bv    = (const float*)d_in[7];
    // d_in[8], d_in[9]: Wsig/bsig are dead code in the reference
    const float* Wo    = (const float*)d_in[10];
    const float* bo    = (const float*)d_in[11];
    const float* W1    = (const float*)d_in[12];
    const float* b1    = (const float*)d_in[13];
    const float* W2    = (const float*)d_in[14];
    const float* b2    = (const float*)d_in[15];
    const float* n1g   = (const float*)d_in[16];
    const float* n1b   = (const float*)d_in[17];
    const float* n2g   = (const float*)d_in[18];
    const float* n2b   = (const float*)d_in[19];
    const float* nfg   = (const float*)d_in[20];
    const float* nfb   = (const float*)d_in[21];
    const float* Wproj = (const float*)d_in[22];
    const float* bproj = (const float*)d_in[23];
    const float* Wfea  = (const float*)d_in[24];
    const float* bfea  = (const float*)d_in[25];
    float* out = (float*)d_out;

    float *h, *x1, *tmp, *bqkv;
    __half *h16,*x1h,*enc16,*qkv,*attnv,*ff1,*xcat,*wt;
    cudaGetSymbolAddress((void**)&h,     g_h);
    cudaGetSymbolAddress((void**)&x1,    g_x1);
    cudaGetSymbolAddress((void**)&tmp,   g_tmp);
    cudaGetSymbolAddress((void**)&bqkv,  g_bqkv);
    cudaGetSymbolAddress((void**)&h16,   g_h16);
    cudaGetSymbolAddress((void**)&x1h,   g_x1h);
    cudaGetSymbolAddress((void**)&enc16, g_enc16);
    cudaGetSymbolAddress((void**)&qkv,   g_qkv);
    cudaGetSymbolAddress((void**)&attnv, g_attnv);
    cudaGetSymbolAddress((void**)&ff1,   g_ff1);
    cudaGetSymbolAddress((void**)&xcat,  g_xcat);
    cudaGetSymbolAddress((void**)&wt,    g_wt);

    // outputs: fea_t | enc_res(384) | rec_temp(512) | emb(512)
    const size_t OFF_FEA = 0;
    const size_t OFF_RES = (size_t)Mn * Dn;
    const size_t OFF_REC = OFF_RES + (size_t)Mn * 384;
    const size_t OFF_EMB = OFF_REC + (size_t)Mn * Dn;
    float* emb = out + OFF_EMB;

    const int SM128 = 3 * (128 + 128) * 72 * 2;   // 110592 B (3 stages, K64 chunks)
    cudaFuncSetAttribute((const void*)gemm_mma<128,2>, cudaFuncAttributeMaxDynamicSharedMemorySize, SM128);
    cudaFuncSetAttribute((const void*)gemm_mma<128,8>, cudaFuncAttributeMaxDynamicSharedMemorySize, SM128);
    cudaFuncSetAttribute((const void*)gemm_mma<128,0>, cudaFuncAttributeMaxDynamicSharedMemorySize, SM128);
    cudaFuncSetAttribute((const void*)flash_attn, cudaFuncAttributeMaxDynamicSharedMemorySize, FL_SMEM);

    // ---- preprocessing ----
    transpose_all<<<9536, dim3(32, 8)>>>(Wq, Wk, Wv, Wo, W1, W2, Wproj, Wfea, wt);
    pack_misc<<<524 + Mn, 128>>>(embk, bq, bk, bv, x, wt + KTF, bqkv, xcat);

    // conv: K=128 -> NC=2 (unrolled)
    gemm_mma<128,2><<<dim3(4, 64), 256, SM128>>>(xcat, 128, wt + KTF, 128, nullptr,
                                                 nullptr, emb, h16, Dn, 128, 0);

    for (int l = 0; l < NLn; l++) {
        const float* hin = (l == 0) ? emb : h;
        size_t o512 = (size_t)l * Dn * Dn, o1 = (size_t)l * Dn * DFFn;
        gemm_mma<128,8><<<dim3(12, 64), 256, SM128>>>(h16, Dn, wt + WQKV(l), Dn,
                                                      bqkv + l * 1536, nullptr,
                                                      nullptr, qkv, 1536, Dn, 0);
        flash_attn<<<dim3(BHn, 16), 256, FL_SMEM>>>(qkv, attnv);
        // Wo GEMM with fused residual add (tmp = hin + attnv@Wo + bo)
        gemm_mma<128,8><<<dim3(4, 64), 256, SM128>>>(attnv, Dn, wt + WTO + o512, Dn,
                                                     bo + l * Dn, hin,
                                                     tmp, nullptr, Dn, Dn, 0);
        add_ln512<<<Mn / 2, dim3(128, 2)>>>(tmp, n1g + l * Dn, n1b + l * Dn, x1, x1h, nullptr);
        gemm_mma<128,8><<<dim3(16, 64), 256, SM128>>>(x1h, Dn, wt + WT1 + o1, Dn,
                                                      b1 + l * DFFn, nullptr,
                                                      nullptr, ff1, DFFn, Dn, 1);
        // W2 GEMM with fused residual add (tmp = x1 + ff1@W2 + b2)
        gemm_mma<128,0><<<dim3(4, 64), 256, SM128>>>(ff1, DFFn, wt + WT2 + o1, DFFn,
                                                     b2 + l * Dn, x1,
                                                     tmp, nullptr, Dn, DFFn, 0);
        add_ln512<<<Mn / 2, dim3(128, 2)>>>(tmp, n2g + l * Dn, n2b + l * Dn, h, h16, nullptr);
    }

    add_ln512<<<Mn / 2, dim3(128, 2)>>>(h, nfg, nfb, nullptr, enc16, out + OFF_RES);

    // fea: K=128 -> NC=2 (unrolled); proj: K=512 -> NC=8 (unrolled)
    gemm_mma<128,2><<<dim3(4, 64), 256, SM128>>>(enc16 + (Dn - DRESn), Dn, wt + WTF, DRESn,
                                                 bfea, nullptr,
                                                 out + OFF_FEA, nullptr, Dn, DRESn, 0);
    gemm_mma<128,8><<<dim3(4, 64), 256, SM128>>>(enc16, Dn, wt + WTP, Dn,
                                                 bproj, nullptr,
                                                 out + OFF_REC, nullptr, Dn, Dn, 0);
}

// round 14
// speedup vs baseline: 1.0583x; 1.0583x over previous
#include <cuda_runtime.h>
#include <cuda.h>
#include <cuda_fp16.h>
#include <math.h>

#define Bn   16
#define Ln   512
#define Cn   38
#define Dn   512
#define Hn   8
#define En   64
#define DFFn 2048
#define NLn  3
#define DRESn 128
#define Mn   (Bn*Ln)     /* 8192 */
#define BHn  (Bn*Hn)     /* 128  */

// ---------------- scratch (static device memory) ----------------
__device__ float  g_h   [Mn*Dn];
__device__ float  g_x1  [Mn*Dn];
__device__ float  g_tmp [Mn*Dn];
__device__ __align__(16) __half g_h16  [Mn*Dn];
__device__ __align__(16) __half g_x1h  [Mn*Dn];
__device__ __align__(16) __half g_enc16[Mn*Dn];
__device__ __align__(16) __half g_qkv  [Mn*1536];
__device__ __align__(16) __half g_attnv[Mn*Dn];
__device__ __align__(16) __half g_ff1  [Mn*DFFn];
__device__ __align__(16) __half g_xcat [Mn*128];
__device__ __align__(16) __half g_wt   [9830400];     // transposed weights (half)
__device__ float  g_bqkv[NLn*1536];

#define WQKV(l) ((size_t)(l) * 786432)                 /* fused [1536][512] per layer */
#define WTO 2359296
#define WT1 3145728
#define WT2 6291456
#define WTP 9437184
#define WTF 9699328
#define KTF 9764864

// ================= helpers =================
__device__ __forceinline__ unsigned smem_u32(const void* p) {
    unsigned a;
    asm("{ .reg .u64 t; cvta.to.shared.u64 t, %1; cvt.u32.u64 %0, t; }"
        : "=r"(a) : "l"(p));
    return a;
}
__device__ __forceinline__ void mma16(float* c, const unsigned* a, const unsigned* b) {
    asm volatile("mma.sync.aligned.m16n8k16.row.col.f32.f16.f16.f32 "
        "{%0,%1,%2,%3}, {%4,%5,%6,%7}, {%8,%9}, {%0,%1,%2,%3};"
        : "+f"(c[0]), "+f"(c[1]), "+f"(c[2]), "+f"(c[3])
        : "r"(a[0]), "r"(a[1]), "r"(a[2]), "r"(a[3]), "r"(b[0]), "r"(b[1]));
}
__device__ __forceinline__ void ldsm4(unsigned* r, unsigned addr) {
    asm volatile("ldmatrix.sync.aligned.m8n8.x4.shared.b16 {%0,%1,%2,%3}, [%4];"
        : "=r"(r[0]), "=r"(r[1]), "=r"(r[2]), "=r"(r[3]) : "r"(addr));
}
__device__ __forceinline__ void ldsm4t(unsigned* r, unsigned addr) {
    asm volatile("ldmatrix.sync.aligned.m8n8.x4.trans.shared.b16 {%0,%1,%2,%3}, [%4];"
        : "=r"(r[0]), "=r"(r[1]), "=r"(r[2]), "=r"(r[3]) : "r"(addr));
}
__device__ __forceinline__ unsigned h2u(__half2 v) { return *(unsigned*)&v; }
#define CP16(sa, gp) \
    asm volatile("cp.async.cg.shared.global [%0], [%1], 16;" :: "r"(sa), "l"(gp))
#define CPCOMMIT() asm volatile("cp.async.commit_group;" ::: "memory")
#define CPWAIT(n)  asm volatile("cp.async.wait_group %0;" :: "n"(n) : "memory")

// == fp16 tensor-core GEMM (3-stage pipeline, K-chunk 64, templated trips) ===
// NCT > 0: compile-time chunk count (fully unrolled). NCT == 0: runtime (K/64).
template<int NT, int NCT>
__global__ __launch_bounds__(256, 2)
void gemm_mma(const __half* __restrict__ A, int lda,
              const __half* __restrict__ BT, int ldb,
              const float* __restrict__ bias,
              float* __restrict__ C, __half* __restrict__ C16, int ldc,
              int K, int do_gelu)
{
    constexpr int WC  = 4;
    constexpr int WM  = 64;
    constexpr int MT  = WM / 16;
    constexpr int RS  = 72;                   // 64 data halves + 8 pad
    constexpr int STG = (128 + NT) * RS;      // halves per stage

    extern __shared__ __align__(16) char dsm[];
    __half* sm = (__half*)dsm;
    const int tid = threadIdx.x, w = tid >> 5, lane = tid & 31;
    const int m0 = blockIdx.y * 128, n0 = blockIdx.x * NT;
    const int g = lane >> 3, lr = lane & 7;

    auto load_stage = [&](int kc, int st) {
        __half* As = sm + st * STG;
        __half* Bs = As + 128 * RS;
        const __half* Ap = A + (size_t)m0 * lda + kc * 64;
#pragma unroll
        for (int i = 0; i < 4; i++) {
            int fi = tid + i * 256, row = fi >> 3, seg = fi & 7;
            CP16(smem_u32(As + row * RS + seg * 8), Ap + (size_t)row * lda + seg * 8);
        }
        const __half* Bp = BT + (size_t)n0 * ldb + kc * 64;
#pragma unroll
        for (int i = 0; i < NT / 32; i++) {
            int fi = tid + i * 256, row = fi >> 3, seg = fi & 7;
            CP16(smem_u32(Bs + row * RS + seg * 8), Bp + (size_t)row * ldb + seg * 8);
        }
    };

    float acc[MT][4][4];
#pragma unroll
    for (int mt = 0; mt < MT; mt++)
#pragma unroll
        for (int nt = 0; nt < 4; nt++)
#pragma unroll
            for (int j = 0; j < 4; j++) acc[mt][nt][j] = 0.f;

    const int wm0 = (w / WC) * WM, wn0 = (w % WC) * 32;
    const int r = lane >> 2, cl = lane & 3;
    const unsigned aLane = ((g & 1) * 8 + lr) * RS + (g >> 1) * 8;
    const unsigned bLane = ((g >> 1) * 8 + lr) * RS + (g & 1) * 8;

    auto compute = [&](int st) {
        __half* As = sm + st * STG;
        __half* Bs = As + 128 * RS;
        unsigned aBase = smem_u32(As) + 2u * (wm0 * RS + aLane);
        unsigned bBase = smem_u32(Bs) + 2u * (wn0 * RS + bLane);
#pragma unroll
        for (int ks = 0; ks < 4; ks++) {          // four k16 steps per 64-chunk
            const unsigned koff = ks * 32;
            unsigned a[MT][4], b[4][2];
#pragma unroll
            for (int mt = 0; mt < MT; mt++)
                ldsm4(a[mt], aBase + mt * (16 * RS * 2) + koff);
#pragma unroll
            for (int p = 0; p < 2; p++) {
                unsigned t[4];
                ldsm4(t, bBase + p * (16 * RS * 2) + koff);
                b[2 * p][0] = t[0]; b[2 * p][1] = t[1];
                b[2 * p + 1][0] = t[2]; b[2 * p + 1][1] = t[3];
            }
#pragma unroll
            for (int mt = 0; mt < MT; mt++)
#pragma unroll
                for (int nt = 0; nt < 4; nt++)
                    mma16(acc[mt][nt], a[mt], b[nt]);
        }
    };

    auto step = [&](int c, int NCloc) {
        if (c + 1 < NCloc) { CPWAIT(1); }      // chunk c landed; c+1 may fly
        else              { CPWAIT(0); }       // final chunk fully landed
        __syncthreads();
        compute(c % 3);
        if (c + 2 < NCloc) {
            load_stage(c + 2, (c + 2) % 3);
            CPCOMMIT();
        }
    };

    load_stage(0, 0); CPCOMMIT();
    load_stage(1, 1); CPCOMMIT();

    if constexpr (NCT > 0) {
#pragma unroll
        for (int c = 0; c < NCT; c++) step(c, NCT);
    } else {
        const int NC = K >> 6;
#pragma unroll 4
        for (int c = 0; c < NC; c++) step(c, NC);
    }

#pragma unroll
    for (int mt = 0; mt < MT; mt++) {
#pragma unroll
        for (int nt = 0; nt < 4; nt++) {
            int row = m0 + wm0 + mt * 16 + r;
            int col = n0 + wn0 + nt * 8 + cl * 2;
            float bs0 = bias ? bias[col] : 0.f;
            float bs1 = bias ? bias[col + 1] : 0.f;
            float v0 = acc[mt][nt][0] + bs0;
            float v1 = acc[mt][nt][1] + bs1;
            float v2 = acc[mt][nt][2] + bs0;
            float v3 = acc[mt][nt][3] + bs1;
            if (do_gelu) {
                v0 = 0.5f * v0 * (1.0f + erff(v0 * 0.70710678118654752f));
                v1 = 0.5f * v1 * (1.0f + erff(v1 * 0.70710678118654752f));
                v2 = 0.5f * v2 * (1.0f + erff(v2 * 0.70710678118654752f));
                v3 = 0.5f * v3 * (1.0f + erff(v3 * 0.70710678118654752f));
            }
            if (C) {
                float* p0 = C + (size_t)row * ldc + col;
                float* p1 = p0 + (size_t)8 * ldc;
                p0[0] = v0; p0[1] = v1;
                p1[0] = v2; p1[1] = v3;
            }
            if (C16) {
                *(__half2*)(C16 + (size_t)row * ldc + col) = __floats2half2_rn(v0, v1);
                *(__half2*)(C16 + (size_t)(row + 8) * ldc + col) = __floats2half2_rn(v2, v3);
            }
        }
    }
}

// ================= flash attention: scores + softmax + P.V ==================
#define FL_RSQ 72
#define FL_RSK 72
#define FL_RSV 72
#define FL_KOFF (32*FL_RSQ)                    /* halves */
#define FL_VOFF (FL_KOFF + 512*FL_RSK)
#define FL_REDB ((FL_VOFF + 512*FL_RSV)*2)     /* bytes  */
#define FL_SMEM (FL_REDB + 2048 + 16)

__global__ __launch_bounds__(256, 1)
void flash_attn(const __half* __restrict__ qkv,
                __half* __restrict__ attnv)
{
    extern __shared__ __align__(16) char dsm[];
    __half* Qs = (__half*)dsm;
    __half* Ks = Qs + FL_KOFF;
    __half* Vs = Qs + FL_VOFF;
    float* red  = (float*)(dsm + FL_REDB);
    float* red2 = red + 256;

    const int tid = threadIdx.x, w = tid >> 5, lane = tid & 31;
    const int r = lane >> 2, cl = lane & 3;
    const int g = lane >> 3, lr = lane & 7;
    const int z = blockIdx.x;
    const int m0 = blockIdx.y * 32;
    const int b = z >> 3, hh = z & 7;
    const size_t qbase = ((size_t)b * Ln) * 1536 + (size_t)hh * 64;

    {
        int row = tid >> 3, seg = tid & 7;
        *(uint4*)(Qs + row * FL_RSQ + seg * 8) =
            *(const uint4*)(qkv + qbase + (size_t)(m0 + row) * 1536 + seg * 8);
    }
#pragma unroll 4
    for (int i = 0; i < 16; i++) {
        int idx = tid + i * 256, row = idx >> 3, seg = idx & 7;
        const __half* src = qkv + qbase + 512 + (size_t)row * 1536 + seg * 8;
        *(uint4*)(Ks + row * FL_RSK + seg * 8) = *(const uint4*)src;
        *(uint4*)(Vs + row * FL_RSV + seg * 8) = *(const uint4*)(src + 512);
    }
    __syncthreads();

    const int wn0 = w * 64;
    float acc[2][8][4];
#pragma unroll
    for (int mt = 0; mt < 2; mt++)
#pragma unroll
        for (int nt = 0; nt < 8; nt++)
#pragma unroll
            for (int j = 0; j < 4; j++) acc[mt][nt][j] = 0.f;

    const unsigned aBase = smem_u32(Qs) + 2u * (((g & 1) * 8 + lr) * FL_RSQ + (g >> 1) * 8);
    const unsigned bBase = smem_u32(Ks) + 2u * ((wn0 + (g >> 1) * 8 + lr) * FL_RSK + (g & 1) * 8);
#pragma unroll
    for (int ks = 0; ks < 4; ks++) {
        const unsigned koff = ks * 32;
        unsigned a[2][4], b[8][2];
#pragma unroll
        for (int mt = 0; mt < 2; mt++)
            ldsm4(a[mt], aBase + mt * (16 * FL_RSQ * 2) + koff);
#pragma unroll
        for (int p = 0; p < 4; p++) {
            unsigned t[4];
            ldsm4(t, bBase + p * (16 * FL_RSK * 2) + koff);
            b[2 * p][0] = t[0]; b[2 * p][1] = t[1];
            b[2 * p + 1][0] = t[2]; b[2 * p + 1][1] = t[3];
        }
#pragma unroll
        for (int mt = 0; mt < 2; mt++)
#pragma unroll
            for (int nt = 0; nt < 8; nt++)
                mma16(acc[mt][nt], a[mt], b[nt]);
    }

    float M[4], inv[4];
#pragma unroll
    for (int rs = 0; rs < 4; rs++) {
        int mt = rs >> 1, jb = (rs & 1) * 2;
        float mx = -1e30f;
#pragma unroll
        for (int nt = 0; nt < 8; nt++)
            mx = fmaxf(mx, fmaxf(acc[mt][nt][jb], acc[mt][nt][jb + 1]));
        mx = fmaxf(mx, __shfl_xor_sync(0xFFFFFFFFu, mx, 1));
        mx = fmaxf(mx, __shfl_xor_sync(0xFFFFFFFFu, mx, 2));
        if (cl == 0) red[w * 32 + mt * 16 + r + (rs & 1) * 8] = mx;
    }
    __syncthreads();
#pragma unroll
    for (int rs = 0; rs < 4; rs++) {
        int row = (rs >> 1) * 16 + r + (rs & 1) * 8;
        float mx = -1e30f;
#pragma unroll
        for (int w2 = 0; w2 < 8; w2++) mx = fmaxf(mx, red[w2 * 32 + row]);
        M[rs] = mx;
    }
#pragma unroll
    for (int rs = 0; rs < 4; rs++) {
        int mt = rs >> 1, jb = (rs & 1) * 2;
        float s = 0.f;
#pragma unroll
        for (int nt = 0; nt < 8; nt++) {
            float e0 = __expf((acc[mt][nt][jb]     - M[rs]) * 0.125f);
            float e1 = __expf((acc[mt][nt][jb + 1] - M[rs]) * 0.125f);
            acc[mt][nt][jb] = e0; acc[mt][nt][jb + 1] = e1;
            s += e0 + e1;
        }
        s += __shfl_xor_sync(0xFFFFFFFFu, s, 1);
        s += __shfl_xor_sync(0xFFFFFFFFu, s, 2);
        if (cl == 0) red2[w * 32 + mt * 16 + r + (rs & 1) * 8] = s;
    }
    __syncthreads();
#pragma unroll
    for (int rs = 0; rs < 4; rs++) {
        int row = (rs >> 1) * 16 + r + (rs & 1) * 8;
        float s = 0.f;
#pragma unroll
        for (int w2 = 0; w2 < 8; w2++) s += red2[w2 * 32 + row];
        inv[rs] = 1.0f / s;
    }

    float o[2][8][4];
#pragma unroll
    for (int mt = 0; mt < 2; mt++)
#pragma unroll
        for (int nt = 0; nt < 8; nt++)
#pragma unroll
            for (int j = 0; j < 4; j++) o[mt][nt][j] = 0.f;

    const unsigned vBase = smem_u32(Vs) + 2u * ((wn0 + (g & 1) * 8 + lr) * FL_RSV + (g >> 1) * 8);
#pragma unroll
    for (int t = 0; t < 4; t++) {
        unsigned a[2][4], b[8][2];
#pragma unroll
        for (int mt = 0; mt < 2; mt++) {
            a[mt][0] = h2u(__floats2half2_rn(acc[mt][2*t][0]   * inv[2*mt],     acc[mt][2*t][1]   * inv[2*mt]));
            a[mt][1] = h2u(__floats2half2_rn(acc[mt][2*t][2]   * inv[2*mt + 1], acc[mt][2*t][3]   * inv[2*mt + 1]));
            a[mt][2] = h2u(__floats2half2_rn(acc[mt][2*t+1][0] * inv[2*mt],     acc[mt][2*t+1][1] * inv[2*mt]));
            a[mt][3] = h2u(__floats2half2_rn(acc[mt][2*t+1][2] * inv[2*mt + 1], acc[mt][2*t+1][3] * inv[2*mt + 1]));
        }
#pragma unroll
        for (int p = 0; p < 4; p++) {
            unsigned tb[4];
            ldsm4t(tb, vBase + t * (16 * FL_RSV * 2) + p * 32);
            b[2 * p][0] = tb[0]; b[2 * p][1] = tb[1];
            b[2 * p + 1][0] = tb[2]; b[2 * p + 1][1] = tb[3];
        }
#pragma unroll
        for (int mt = 0; mt < 2; mt++)
#pragma unroll
            for (int nt = 0; nt < 8; nt++)
                mma16(o[mt][nt], a[mt], b[nt]);
    }

    float* part = (float*)(dsm + FL_KOFF * 2);
#pragma unroll
    for (int mt = 0; mt < 2; mt++)
#pragma unroll
        for (int nt = 0; nt < 8; nt++) {
            int row = mt * 16 + r, col = nt * 8 + cl * 2;
            float* p = part + w * 2112 + row * 66 + col;
            p[0] = o[mt][nt][0]; p[1] = o[mt][nt][1];
            p[8 * 66] = o[mt][nt][2]; p[8 * 66 + 1] = o[mt][nt][3];
        }
    __syncthreads();

    {
        int orow = tid >> 3, c0 = (tid & 7) * 8;
        float s[8];
#pragma unroll
        for (int c = 0; c < 8; c++) s[c] = 0.f;
#pragma unroll
        for (int w2 = 0; w2 < 8; w2++) {
            const float* p = part + w2 * 2112 + orow * 66 + c0;
#pragma unroll
            for (int c = 0; c < 8; c++) s[c] += p[c];
        }
        __align__(16) __half2 hb[4];
#pragma unroll
        for (int c = 0; c < 4; c++) hb[c] = __floats2half2_rn(s[2 * c], s[2 * c + 1]);
        *(uint4*)(attnv + ((size_t)b * Ln + m0 + orow) * Dn + hh * 64 + c0) = *(uint4*)hb;
    }
}

// ================= batched weight transpose (ALL weights, one launch) =======
__global__ void transpose_all(const float* __restrict__ Wq, const float* __restrict__ Wk,
                              const float* __restrict__ Wv, const float* __restrict__ Wo,
                              const float* __restrict__ W1, const float* __restrict__ W2,
                              const float* __restrict__ Wproj, const float* __restrict__ Wfea,
                              __half* __restrict__ wt)
{
    int bid = blockIdx.x;
    const float* in; __half* out; int K, N, bx, by;
    if (bid < 9216) {
        int l = bid / 3072, rr = bid - l * 3072;
        size_t o512 = (size_t)l * 262144, o1 = (size_t)l * 1048576;
        if (rr < 1024) {
            int m = rr >> 8, idx = rr & 255;
            K = 512; N = 512; bx = idx & 15; by = idx >> 4;
            if (m == 0)      { in = Wq + o512; out = wt + WQKV(l); }
            else if (m == 1) { in = Wk + o512; out = wt + WQKV(l) + 262144; }
            else if (m == 2) { in = Wv + o512; out = wt + WQKV(l) + 524288; }
            else             { in = Wo + o512; out = wt + WTO + o512; }
        } else if (rr < 2048) {
            int idx = rr - 1024;
            K = 512; N = 2048; bx = idx & 63; by = idx >> 6;
            in = W1 + o1; out = wt + WT1 + o1;
        } else {
            int idx = rr - 2048;
            K = 2048; N = 512; bx = idx & 15; by = idx >> 4;
            in = W2 + o1; out = wt + WT2 + o1;
        }
    } else if (bid < 9472) {
        int idx = bid - 9216;
        K = 512; N = 512; bx = idx & 15; by = idx >> 4;
        in = Wproj; out = wt + WTP;
    } else {
        int idx = bid - 9472;
        K = 128; N = 512; bx = idx & 15; by = idx >> 4;
        in = Wfea; out = wt + WTF;
    }
    __shared__ float t[32][33];
    int k0 = by * 32, n0 = bx * 32;
    int tx = threadIdx.x, ty = threadIdx.y;
#pragma unroll
    for (int rr2 = 0; rr2 < 4; rr2++)
        t[ty + rr2 * 8][tx] = in[(size_t)(k0 + ty + rr2 * 8) * N + n0 + tx];
    __syncthreads();
#pragma unroll
    for (int rr2 = 0; rr2 < 4; rr2++)
        out[(size_t)(n0 + ty + rr2 * 8) * K + k0 + tx] = __float2half(t[tx][ty + rr2 * 8]);
}

// ================= combined small packs: ktf | bqkv | xcat ==================
__global__ void pack_misc(const float* __restrict__ kern,
                          const float* __restrict__ bq, const float* __restrict__ bk,
                          const float* __restrict__ bv,
                          const float* __restrict__ x,
                          __half* __restrict__ kt, float* __restrict__ bdst,
                          __half* __restrict__ xc)
{
    int bid = blockIdx.x, tidx = threadIdx.x;
    if (bid < 512) {
        int d = bid;
        kt[(size_t)d * 128 + tidx] =
            __float2half((tidx < Cn * 3) ? kern[(size_t)d * (Cn * 3) + tidx] : 0.f);
    } else if (bid < 524) {
        int j = bid - 512;
        int l = j >> 2, i = (j & 3) * 128 + tidx;
        bdst[l * 1536 + i]        = bq[l * 512 + i];
        bdst[l * 1536 + 512 + i]  = bk[l * 512 + i];
        bdst[l * 1536 + 1024 + i] = bv[l * 512 + i];
    } else {
        int bl = bid - 524;
        int b = bl >> 9, l = bl & 511;
        float val = 0.f;
        if (tidx < Cn * 3) {
            int c = tidx / 3, t = tidx - c * 3;
            int ls = (l - 1 + t + Ln) & (Ln - 1);
            val = x[((size_t)b * Ln + ls) * Cn + c];
        }
        xc[(size_t)bl * 128 + tidx] = __float2half(val);
    }
}

// ===== layernorm (two-input, 128 thr x float4) =====
__global__ void add_ln512(const float* __restrict__ a, const float* __restrict__ b,
                          const float* __restrict__ g, const float* __restrict__ be,
                          float* __restrict__ o, __half* __restrict__ o16,
                          float* __restrict__ res) {
    int row = blockIdx.x, t = threadIdx.x;        // 128 threads
    size_t base = (size_t)row * Dn;
    float4 v = *(const float4*)(a + base + t * 4);
    if (b) {
        float4 vb = *(const float4*)(b + base + t * 4);
        v.x += vb.x; v.y += vb.y; v.z += vb.z; v.w += vb.w;
    }
    float s = v.x + v.y + v.z + v.w;
#pragma unroll
    for (int oo = 16; oo > 0; oo >>= 1) s += __shfl_xor_sync(0xFFFFFFFFu, s, oo);
    __shared__ float s1[4], s2[4];
    if ((t & 31) == 0) s1[t >> 5] = s;
    __syncthreads();
    float mean = (s1[0] + s1[1] + s1[2] + s1[3]) * (1.0f / Dn);
    float d0 = v.x - mean, d1 = v.y - mean, d2 = v.z - mean, d3 = v.w - mean;
    float q2 = d0 * d0 + d1 * d1 + d2 * d2 + d3 * d3;
#pragma unroll
    for (int oo = 16; oo > 0; oo >>= 1) q2 += __shfl_xor_sync(0xFFFFFFFFu, q2, oo);
    if ((t & 31) == 0) s2[t >> 5] = q2;
    __syncthreads();
    float var = (s2[0] + s2[1] + s2[2] + s2[3]) * (1.0f / Dn);
    float rr = rsqrtf(var + 1e-5f);
    float4 gg = *(const float4*)(g + t * 4);
    float4 bb = *(const float4*)(be + t * 4);
    float o0 = d0 * rr * gg.x + bb.x;
    float o1 = d1 * rr * gg.y + bb.y;
    float o2 = d2 * rr * gg.z + bb.z;
    float o3 = d3 * rr * gg.w + bb.w;
    if (o) {
        float4 ov = {o0, o1, o2, o3};
        *(float4*)(o + base + t * 4) = ov;
    }
    if (o16) {
        *(__half2*)(o16 + base + t * 4)     = __floats2half2_rn(o0, o1);
        *(__half2*)(o16 + base + t * 4 + 2) = __floats2half2_rn(o2, o3);
    }
    if (res && t < 96) {
        float4 rv = {o0, o1, o2, o3};
        *(float4*)(res + (size_t)row * 384 + t * 4) = rv;
    }
}

// ================= launcher =================
extern "C" void kernel_launch(void* const* d_in, const int* in_sizes, int n_in,
                              void* d_out, int out_size)
{
    const float* x     = (const float*)d_in[0];
    const float* embk  = (const float*)d_in[1];
    const float* Wq    = (const float*)d_in[2];
    const float* bq    = (const float*)d_in[3];
    const float* Wk    = (const float*)d_in[4];
    const float* bk    = (const float*)d_in[5];
    const float* Wv    = (const float*)d_in[6];
    const float* bv    = (const float*)d_in[7];
    // d_in[8], d_in[9]: Wsig/bsig are dead code in the reference
    const float* Wo    = (const float*)d_in[10];
    const float* bo    = (const float*)d_in[11];
    const float* W1    = (const float*)d_in[12];
    const float* b1    = (const float*)d_in[13];
    const float* W2    = (const float*)d_in[14];
    const float* b2    = (const float*)d_in[15];
    const float* n1g   = (const float*)d_in[16];
    const float* n1b   = (const float*)d_in[17];
    const float* n2g   = (const float*)d_in[18];
    const float* n2b   = (const float*)d_in[19];
    const float* nfg   = (const float*)d_in[20];
    const float* nfb   = (const float*)d_in[21];
    const float* Wproj = (const float*)d_in[22];
    const float* bproj = (const float*)d_in[23];
    const float* Wfea  = (const float*)d_in[24];
    const float* bfea  = (const float*)d_in[25];
    float* out = (float*)d_out;

    float *h, *x1, *tmp, *bqkv;
    __half *h16,*x1h,*enc16,*qkv,*attnv,*ff1,*xcat,*wt;
    cudaGetSymbolAddress((void**)&h,     g_h);
    cudaGetSymbolAddress((void**)&x1,    g_x1);
    cudaGetSymbolAddress((void**)&tmp,   g_tmp);
    cudaGetSymbolAddress((void**)&bqkv,  g_bqkv);
    cudaGetSymbolAddress((void**)&h16,   g_h16);
    cudaGetSymbolAddress((void**)&x1h,   g_x1h);
    cudaGetSymbolAddress((void**)&enc16, g_enc16);
    cudaGetSymbolAddress((void**)&qkv,   g_qkv);
    cudaGetSymbolAddress((void**)&attnv, g_attnv);
    cudaGetSymbolAddress((void**)&ff1,   g_ff1);
    cudaGetSymbolAddress((void**)&xcat,  g_xcat);
    cudaGetSymbolAddress((void**)&wt,    g_wt);

    // outputs: fea_t | enc_res(384) | rec_temp(512) | emb(512)
    const size_t OFF_FEA = 0;
    const size_t OFF_RES = (size_t)Mn * Dn;
    const size_t OFF_REC = OFF_RES + (size_t)Mn * 384;
    const size_t OFF_EMB = OFF_REC + (size_t)Mn * Dn;
    float* emb = out + OFF_EMB;

    const int SM128 = 3 * (128 + 128) * 72 * 2;   // 110592 B (3 stages, K64 chunks)
    cudaFuncSetAttribute((const void*)gemm_mma<128,2>, cudaFuncAttributeMaxDynamicSharedMemorySize, SM128);
    cudaFuncSetAttribute((const void*)gemm_mma<128,8>, cudaFuncAttributeMaxDynamicSharedMemorySize, SM128);
    cudaFuncSetAttribute((const void*)gemm_mma<128,0>, cudaFuncAttributeMaxDynamicSharedMemorySize, SM128);
    cudaFuncSetAttribute((const void*)flash_attn, cudaFuncAttributeMaxDynamicSharedMemorySize, FL_SMEM);

    // ---- preprocessing ----
    transpose_all<<<9536, dim3(32, 8)>>>(Wq, Wk, Wv, Wo, W1, W2, Wproj, Wfea, wt);
    pack_misc<<<524 + Mn, 128>>>(embk, bq, bk, bv, x, wt + KTF, bqkv, xcat);

    // conv: K=128 -> NC=2 (unrolled)
    gemm_mma<128,2><<<dim3(4, 64), 256, SM128>>>(xcat, 128, wt + KTF, 128, nullptr,
                                                 emb, h16, Dn, 128, 0);

    for (int l = 0; l < NLn; l++) {
        const float* hin = (l == 0) ? emb : h;
        size_t o512 = (size_t)l * Dn * Dn, o1 = (size_t)l * Dn * DFFn;
        gemm_mma<128,8><<<dim3(12, 64), 256, SM128>>>(h16, Dn, wt + WQKV(l), Dn,
                                                      bqkv + l * 1536, nullptr, qkv, 1536, Dn, 0);
        flash_attn<<<dim3(BHn, 16), 256, FL_SMEM>>>(qkv, attnv);
        gemm_mma<128,8><<<dim3(4, 64), 256, SM128>>>(attnv, Dn, wt + WTO + o512, Dn,
                                                     bo + l * Dn, tmp, nullptr, Dn, Dn, 0);
        add_ln512<<<Mn, 128>>>(hin, tmp, n1g + l * Dn, n1b + l * Dn, x1, x1h, nullptr);
        gemm_mma<128,8><<<dim3(16, 64), 256, SM128>>>(x1h, Dn, wt + WT1 + o1, Dn,
                                                      b1 + l * DFFn, nullptr, ff1, DFFn, Dn, 1);
        gemm_mma<128,0><<<dim3(4, 64), 256, SM128>>>(ff1, DFFn, wt + WT2 + o1, DFFn,
                                                     b2 + l * Dn, tmp, nullptr, Dn, DFFn, 0);
        add_ln512<<<Mn, 128>>>(x1, tmp, n2g + l * Dn, n2b + l * Dn, h, h16, nullptr);
    }

    add_ln512<<<Mn, 128>>>(h, nullptr, nfg, nfb, nullptr, enc16, out + OFF_RES);

    // fea: K=128 -> NC=2 (unrolled); proj: K=512 -> NC=8 (unrolled)
    gemm_mma<128,2><<<dim3(4, 64), 256, SM128>>>(enc16 + (Dn - DRESn), Dn, wt + WTF, DRESn,
                                                 bfea, out + OFF_FEA, nullptr, Dn, DRESn, 0);
    gemm_mma<128,8><<<dim3(4, 64), 256, SM128>>>(enc16, Dn, wt + WTP, Dn,
                                                 bproj, out + OFF_REC, nullptr, Dn, Dn, 0);
}

// round 15
// speedup vs baseline: 1.0827x; 1.0231x over previous
#include <cuda_runtime.h>
#include <cuda.h>
#include <cuda_fp16.h>
#include <math.h>

#define Bn   16
#define Ln   512
#define Cn   38
#define Dn   512
#define Hn   8
#define En   64
#define DFFn 2048
#define NLn  3
#define DRESn 128
#define Mn   (Bn*Ln)     /* 8192 */
#define BHn  (Bn*Hn)     /* 128  */

// ---------------- scratch (static device memory) ----------------
__device__ float  g_h   [Mn*Dn];
__device__ float  g_x1  [Mn*Dn];
__device__ float  g_tmp [Mn*Dn];
__device__ __align__(16) __half g_h16  [Mn*Dn];
__device__ __align__(16) __half g_x1h  [Mn*Dn];
__device__ __align__(16) __half g_enc16[Mn*Dn];
__device__ __align__(16) __half g_qkv  [Mn*1536];
__device__ __align__(16) __half g_attnv[Mn*Dn];
__device__ __align__(16) __half g_ff1  [Mn*DFFn];
__device__ __align__(16) __half g_xcat [Mn*128];
__device__ __align__(16) __half g_wt   [10027008];    // transposed weights (half)
__device__ float  g_bqkv[NLn*1536];
__device__ float  g_btail[1024];                      // bproj | bfea

#define WQKV(l) ((size_t)(l) * 786432)                 /* fused [1536][512] per layer */
#define WTO 2359296
#define WT1 3145728
#define WT2 6291456
#define WTP 9437184
#define WTF 9699328   /* fea zero-padded to [512][512], contiguous after WTP */
#define KTF 9961472

// ================= helpers =================
__device__ __forceinline__ unsigned smem_u32(const void* p) {
    unsigned a;
    asm("{ .reg .u64 t; cvta.to.shared.u64 t, %1; cvt.u32.u64 %0, t; }"
        : "=r"(a) : "l"(p));
    return a;
}
__device__ __forceinline__ void mma16(float* c, const unsigned* a, const unsigned* b) {
    asm volatile("mma.sync.aligned.m16n8k16.row.col.f32.f16.f16.f32 "
        "{%0,%1,%2,%3}, {%4,%5,%6,%7}, {%8,%9}, {%0,%1,%2,%3};"
        : "+f"(c[0]), "+f"(c[1]), "+f"(c[2]), "+f"(c[3])
        : "r"(a[0]), "r"(a[1]), "r"(a[2]), "r"(a[3]), "r"(b[0]), "r"(b[1]));
}
__device__ __forceinline__ void ldsm4(unsigned* r, unsigned addr) {
    asm volatile("ldmatrix.sync.aligned.m8n8.x4.shared.b16 {%0,%1,%2,%3}, [%4];"
        : "=r"(r[0]), "=r"(r[1]), "=r"(r[2]), "=r"(r[3]) : "r"(addr));
}
__device__ __forceinline__ void ldsm4t(unsigned* r, unsigned addr) {
    asm volatile("ldmatrix.sync.aligned.m8n8.x4.trans.shared.b16 {%0,%1,%2,%3}, [%4];"
        : "=r"(r[0]), "=r"(r[1]), "=r"(r[2]), "=r"(r[3]) : "r"(addr));
}
__device__ __forceinline__ unsigned h2u(__half2 v) { return *(unsigned*)&v; }
#define CP16(sa, gp) \
    asm volatile("cp.async.cg.shared.global [%0], [%1], 16;" :: "r"(sa), "l"(gp))
#define CPCOMMIT() asm volatile("cp.async.commit_group;" ::: "memory")
#define CPWAIT(n)  asm volatile("cp.async.wait_group %0;" :: "n"(n) : "memory")

// == fp16 tensor-core GEMM (3-stage pipeline, K-chunk 64, templated trips) ===
// NCT > 0: compile-time chunk count (fully unrolled). NCT == 0: runtime (K/64).
// C2: optional second fp32 output; n-blocks with n0>=512 write to C2 instead
//     (address C2 - 512 + row*ldc + col), used by the merged proj|fea tail.
template<int NT, int NCT>
__global__ __launch_bounds__(256, 2)
void gemm_mma(const __half* __restrict__ A, int lda,
              const __half* __restrict__ BT, int ldb,
              const float* __restrict__ bias,
              float* __restrict__ C, __half* __restrict__ C16, int ldc,
              int K, int do_gelu, float* __restrict__ C2)
{
    constexpr int WC  = 4;
    constexpr int WM  = 64;
    constexpr int MT  = WM / 16;
    constexpr int RS  = 72;                   // 64 data halves + 8 pad
    constexpr int STG = (128 + NT) * RS;      // halves per stage

    extern __shared__ __align__(16) char dsm[];
    __half* sm = (__half*)dsm;
    const int tid = threadIdx.x, w = tid >> 5, lane = tid & 31;
    const int m0 = blockIdx.y * 128, n0 = blockIdx.x * NT;
    const int g = lane >> 3, lr = lane & 7;

    auto load_stage = [&](int kc, int st) {
        __half* As = sm + st * STG;
        __half* Bs = As + 128 * RS;
        const __half* Ap = A + (size_t)m0 * lda + kc * 64;
#pragma unroll
        for (int i = 0; i < 4; i++) {
            int fi = tid + i * 256, row = fi >> 3, seg = fi & 7;
            CP16(smem_u32(As + row * RS + seg * 8), Ap + (size_t)row * lda + seg * 8);
        }
        const __half* Bp = BT + (size_t)n0 * ldb + kc * 64;
#pragma unroll
        for (int i = 0; i < NT / 32; i++) {
            int fi = tid + i * 256, row = fi >> 3, seg = fi & 7;
            CP16(smem_u32(Bs + row * RS + seg * 8), Bp + (size_t)row * ldb + seg * 8);
        }
    };

    float acc[MT][4][4];
#pragma unroll
    for (int mt = 0; mt < MT; mt++)
#pragma unroll
        for (int nt = 0; nt < 4; nt++)
#pragma unroll
            for (int j = 0; j < 4; j++) acc[mt][nt][j] = 0.f;

    const int wm0 = (w / WC) * WM, wn0 = (w % WC) * 32;
    const int r = lane >> 2, cl = lane & 3;
    const unsigned aLane = ((g & 1) * 8 + lr) * RS + (g >> 1) * 8;
    const unsigned bLane = ((g >> 1) * 8 + lr) * RS + (g & 1) * 8;

    auto compute = [&](int st) {
        __half* As = sm + st * STG;
        __half* Bs = As + 128 * RS;
        unsigned aBase = smem_u32(As) + 2u * (wm0 * RS + aLane);
        unsigned bBase = smem_u32(Bs) + 2u * (wn0 * RS + bLane);
#pragma unroll
        for (int ks = 0; ks < 4; ks++) {          // four k16 steps per 64-chunk
            const unsigned koff = ks * 32;
            unsigned a[MT][4], b[4][2];
#pragma unroll
            for (int mt = 0; mt < MT; mt++)
                ldsm4(a[mt], aBase + mt * (16 * RS * 2) + koff);
#pragma unroll
            for (int p = 0; p < 2; p++) {
                unsigned t[4];
                ldsm4(t, bBase + p * (16 * RS * 2) + koff);
                b[2 * p][0] = t[0]; b[2 * p][1] = t[1];
                b[2 * p + 1][0] = t[2]; b[2 * p + 1][1] = t[3];
            }
#pragma unroll
            for (int mt = 0; mt < MT; mt++)
#pragma unroll
                for (int nt = 0; nt < 4; nt++)
                    mma16(acc[mt][nt], a[mt], b[nt]);
        }
    };

    auto step = [&](int c, int NCloc) {
        if (c + 1 < NCloc) { CPWAIT(1); }      // chunk c landed; c+1 may fly
        else              { CPWAIT(0); }       // final chunk fully landed
        __syncthreads();
        compute(c % 3);
        if (c + 2 < NCloc) {
            load_stage(c + 2, (c + 2) % 3);
            CPCOMMIT();
        }
    };

    load_stage(0, 0); CPCOMMIT();
    load_stage(1, 1); CPCOMMIT();

    if constexpr (NCT > 0) {
#pragma unroll
        for (int c = 0; c < NCT; c++) step(c, NCT);
    } else {
        const int NC = K >> 6;
#pragma unroll 4
        for (int c = 0; c < NC; c++) step(c, NC);
    }

    float* Cb = C;
    if (C2 && n0 >= 512) Cb = C2 - 512;

#pragma unroll
    for (int mt = 0; mt < MT; mt++) {
#pragma unroll
        for (int nt = 0; nt < 4; nt++) {
            int row = m0 + wm0 + mt * 16 + r;
            int col = n0 + wn0 + nt * 8 + cl * 2;
            float bs0 = bias ? bias[col] : 0.f;
            float bs1 = bias ? bias[col + 1] : 0.f;
            float v0 = acc[mt][nt][0] + bs0;
            float v1 = acc[mt][nt][1] + bs1;
            float v2 = acc[mt][nt][2] + bs0;
            float v3 = acc[mt][nt][3] + bs1;
            if (do_gelu) {
                v0 = 0.5f * v0 * (1.0f + erff(v0 * 0.70710678118654752f));
                v1 = 0.5f * v1 * (1.0f + erff(v1 * 0.70710678118654752f));
                v2 = 0.5f * v2 * (1.0f + erff(v2 * 0.70710678118654752f));
                v3 = 0.5f * v3 * (1.0f + erff(v3 * 0.70710678118654752f));
            }
            if (C) {
                float* p0 = Cb + (size_t)row * ldc + col;
                float* p1 = p0 + (size_t)8 * ldc;
                p0[0] = v0; p0[1] = v1;
                p1[0] = v2; p1[1] = v3;
            }
            if (C16) {
                *(__half2*)(C16 + (size_t)row * ldc + col) = __floats2half2_rn(v0, v1);
                *(__half2*)(C16 + (size_t)(row + 8) * ldc + col) = __floats2half2_rn(v2, v3);
            }
        }
    }
}

// ====== flash attention: 2 m-subtiles per CTA, K/V loaded once ==============
#define FLB 72
#define FL2_KOFF (64*FLB)                       /* halves: Q is 64 rows */
#define FL2_VOFF (FL2_KOFF + 512*FLB)
#define FL2_REDB ((FL2_VOFF + 512*FLB)*2)       /* bytes */
#define FL2_PART (FL2_REDB + 2048)
#define FL2_SMEM (FL2_PART + 4*2112*4 + 16)     /* ~192.5 KB */

__global__ __launch_bounds__(256, 1)
void flash_attn(const __half* __restrict__ qkv,
                __half* __restrict__ attnv)
{
    extern __shared__ __align__(16) char dsm[];
    __half* Qs = (__half*)dsm;
    __half* Ks = Qs + FL2_KOFF;
    __half* Vs = Qs + FL2_VOFF;
    float* red  = (float*)(dsm + FL2_REDB);
    float* red2 = red + 256;
    float* part = (float*)(dsm + FL2_PART);     // 4 x [32][66]

    const int tid = threadIdx.x, w = tid >> 5, lane = tid & 31;
    const int r = lane >> 2, cl = lane & 3;
    const int g = lane >> 3, lr = lane & 7;
    const int z = blockIdx.x;
    const int m0 = blockIdx.y * 64;
    const int b = z >> 3, hh = z & 7;
    const size_t qbase = ((size_t)b * Ln) * 1536 + (size_t)hh * 64;

    // Q: 64 rows
#pragma unroll
    for (int i = 0; i < 2; i++) {
        int idx = tid + i * 256, row = idx >> 3, seg = idx & 7;
        *(uint4*)(Qs + row * FLB + seg * 8) =
            *(const uint4*)(qkv + qbase + (size_t)(m0 + row) * 1536 + seg * 8);
    }
    // K + V: 512 rows each
#pragma unroll 4
    for (int i = 0; i < 16; i++) {
        int idx = tid + i * 256, row = idx >> 3, seg = idx & 7;
        const __half* src = qkv + qbase + 512 + (size_t)row * 1536 + seg * 8;
        *(uint4*)(Ks + row * FLB + seg * 8) = *(const uint4*)src;
        *(uint4*)(Vs + row * FLB + seg * 8) = *(const uint4*)(src + 512);
    }
    __syncthreads();

    const int wn0 = w * 64;
    const unsigned bBase = smem_u32(Ks) + 2u * ((wn0 + (g >> 1) * 8 + lr) * FLB + (g & 1) * 8);
    const unsigned vBase = smem_u32(Vs) + 2u * ((wn0 + (g & 1) * 8 + lr) * FLB + (g >> 1) * 8);

    for (int sub = 0; sub < 2; sub++) {
        const unsigned aBase = smem_u32(Qs) +
            2u * ((sub * 32 + (g & 1) * 8 + lr) * FLB + (g >> 1) * 8);

        // ---- scores ----
        float acc[2][8][4];
#pragma unroll
        for (int mt = 0; mt < 2; mt++)
#pragma unroll
            for (int nt = 0; nt < 8; nt++)
#pragma unroll
                for (int j = 0; j < 4; j++) acc[mt][nt][j] = 0.f;

#pragma unroll
        for (int ks = 0; ks < 4; ks++) {
            const unsigned koff = ks * 32;
            unsigned a[2][4], bf[8][2];
#pragma unroll
            for (int mt = 0; mt < 2; mt++)
                ldsm4(a[mt], aBase + mt * (16 * FLB * 2) + koff);
#pragma unroll
            for (int p = 0; p < 4; p++) {
                unsigned t[4];
                ldsm4(t, bBase + p * (16 * FLB * 2) + koff);
                bf[2 * p][0] = t[0]; bf[2 * p][1] = t[1];
                bf[2 * p + 1][0] = t[2]; bf[2 * p + 1][1] = t[3];
            }
#pragma unroll
            for (int mt = 0; mt < 2; mt++)
#pragma unroll
                for (int nt = 0; nt < 8; nt++)
                    mma16(acc[mt][nt], a[mt], bf[nt]);
        }

        // ---- row softmax over 512 cols ----
        float M[4], inv[4];
#pragma unroll
        for (int rs = 0; rs < 4; rs++) {
            int mt = rs >> 1, jb = (rs & 1) * 2;
            float mx = -1e30f;
#pragma unroll
            for (int nt = 0; nt < 8; nt++)
                mx = fmaxf(mx, fmaxf(acc[mt][nt][jb], acc[mt][nt][jb + 1]));
            mx = fmaxf(mx, __shfl_xor_sync(0xFFFFFFFFu, mx, 1));
            mx = fmaxf(mx, __shfl_xor_sync(0xFFFFFFFFu, mx, 2));
            if (cl == 0) red[w * 32 + mt * 16 + r + (rs & 1) * 8] = mx;
        }
        __syncthreads();
#pragma unroll
        for (int rs = 0; rs < 4; rs++) {
            int row = (rs >> 1) * 16 + r + (rs & 1) * 8;
            float mx = -1e30f;
#pragma unroll
            for (int w2 = 0; w2 < 8; w2++) mx = fmaxf(mx, red[w2 * 32 + row]);
            M[rs] = mx;
        }
#pragma unroll
        for (int rs = 0; rs < 4; rs++) {
            int mt = rs >> 1, jb = (rs & 1) * 2;
            float s = 0.f;
#pragma unroll
            for (int nt = 0; nt < 8; nt++) {
                float e0 = __expf((acc[mt][nt][jb]     - M[rs]) * 0.125f);
                float e1 = __expf((acc[mt][nt][jb + 1] - M[rs]) * 0.125f);
                acc[mt][nt][jb] = e0; acc[mt][nt][jb + 1] = e1;
                s += e0 + e1;
            }
            s += __shfl_xor_sync(0xFFFFFFFFu, s, 1);
            s += __shfl_xor_sync(0xFFFFFFFFu, s, 2);
            if (cl == 0) red2[w * 32 + mt * 16 + r + (rs & 1) * 8] = s;
        }
        __syncthreads();
#pragma unroll
        for (int rs = 0; rs < 4; rs++) {
            int row = (rs >> 1) * 16 + r + (rs & 1) * 8;
            float s = 0.f;
#pragma unroll
            for (int w2 = 0; w2 < 8; w2++) s += red2[w2 * 32 + row];
            inv[rs] = 1.0f / s;
        }

        // ---- P.V ----
        float o[2][8][4];
#pragma unroll
        for (int mt = 0; mt < 2; mt++)
#pragma unroll
            for (int nt = 0; nt < 8; nt++)
#pragma unroll
                for (int j = 0; j < 4; j++) o[mt][nt][j] = 0.f;

#pragma unroll
        for (int t = 0; t < 4; t++) {
            unsigned a[2][4], bf[8][2];
#pragma unroll
            for (int mt = 0; mt < 2; mt++) {
                a[mt][0] = h2u(__floats2half2_rn(acc[mt][2*t][0]   * inv[2*mt],     acc[mt][2*t][1]   * inv[2*mt]));
                a[mt][1] = h2u(__floats2half2_rn(acc[mt][2*t][2]   * inv[2*mt + 1], acc[mt][2*t][3]   * inv[2*mt + 1]));
                a[mt][2] = h2u(__floats2half2_rn(acc[mt][2*t+1][0] * inv[2*mt],     acc[mt][2*t+1][1] * inv[2*mt]));
                a[mt][3] = h2u(__floats2half2_rn(acc[mt][2*t+1][2] * inv[2*mt + 1], acc[mt][2*t+1][3] * inv[2*mt + 1]));
            }
#pragma unroll
            for (int p = 0; p < 4; p++) {
                unsigned tb[4];
                ldsm4t(tb, vBase + t * (16 * FLB * 2) + p * 32);
                bf[2 * p][0] = tb[0]; bf[2 * p][1] = tb[1];
                bf[2 * p + 1][0] = tb[2]; bf[2 * p + 1][1] = tb[3];
            }
#pragma unroll
            for (int mt = 0; mt < 2; mt++)
#pragma unroll
                for (int nt = 0; nt < 8; nt++)
                    mma16(o[mt][nt], a[mt], bf[nt]);
        }

        // ---- two-phase cross-warp reduce (4 buffers) ----
        const int bi = w & 3;
        if (w < 4) {
#pragma unroll
            for (int mt = 0; mt < 2; mt++)
#pragma unroll
                for (int nt = 0; nt < 8; nt++) {
                    int row = mt * 16 + r, col = nt * 8 + cl * 2;
                    float* p = part + bi * 2112 + row * 66 + col;
                    p[0] = o[mt][nt][0]; p[1] = o[mt][nt][1];
                    p[8 * 66] = o[mt][nt][2]; p[8 * 66 + 1] = o[mt][nt][3];
                }
        }
        __syncthreads();
        if (w >= 4) {
#pragma unroll
            for (int mt = 0; mt < 2; mt++)
#pragma unroll
                for (int nt = 0; nt < 8; nt++) {
                    int row = mt * 16 + r, col = nt * 8 + cl * 2;
                    float* p = part + bi * 2112 + row * 66 + col;
                    p[0] += o[mt][nt][0]; p[1] += o[mt][nt][1];
                    p[8 * 66] += o[mt][nt][2]; p[8 * 66 + 1] += o[mt][nt][3];
                }
        }
        __syncthreads();

        {
            int orow = tid >> 3, c0 = (tid & 7) * 8;
            float s[8];
#pragma unroll
            for (int c = 0; c < 8; c++) s[c] = 0.f;
#pragma unroll
            for (int w2 = 0; w2 < 4; w2++) {
                const float* p = part + w2 * 2112 + orow * 66 + c0;
#pragma unroll
                for (int c = 0; c < 8; c++) s[c] += p[c];
            }
            __align__(16) __half2 hb[4];
#pragma unroll
            for (int c = 0; c < 4; c++) hb[c] = __floats2half2_rn(s[2 * c], s[2 * c + 1]);
            *(uint4*)(attnv + ((size_t)b * Ln + m0 + sub * 32 + orow) * Dn + hh * 64 + c0) = *(uint4*)hb;
        }
        __syncthreads();   // protect red/part reuse across subtiles
    }
}

// ================= batched weight transpose (ALL weights, one launch) =======
// WTF job emits fea weights zero-padded to [512 n][512 k] (k<384 -> 0).
__global__ void transpose_all(const float* __restrict__ Wq, const float* __restrict__ Wk,
                              const float* __restrict__ Wv, const float* __restrict__ Wo,
                              const float* __restrict__ W1, const float* __restrict__ W2,
                              const float* __restrict__ Wproj, const float* __restrict__ Wfea,
                              __half* __restrict__ wt)
{
    int bid = blockIdx.x;
    const float* in; __half* out; int K, N, bx, by;
    if (bid < 9216) {
        int l = bid / 3072, rr = bid - l * 3072;
        size_t o512 = (size_t)l * 262144, o1 = (size_t)l * 1048576;
        if (rr < 1024) {
            int m = rr >> 8, idx = rr & 255;
            K = 512; N = 512; bx = idx & 15; by = idx >> 4;
            if (m == 0)      { in = Wq + o512; out = wt + WQKV(l); }
            else if (m == 1) { in = Wk + o512; out = wt + WQKV(l) + 262144; }
            else if (m == 2) { in = Wv + o512; out = wt + WQKV(l) + 524288; }
            else             { in = Wo + o512; out = wt + WTO + o512; }
        } else if (rr < 2048) {
            int idx = rr - 1024;
            K = 512; N = 2048; bx = idx & 63; by = idx >> 6;
            in = W1 + o1; out = wt + WT1 + o1;
        } else {
            int idx = rr - 2048;
            K = 2048; N = 512; bx = idx & 15; by = idx >> 4;
            in = W2 + o1; out = wt + WT2 + o1;
        }
    } else if (bid < 9472) {
        int idx = bid - 9216;
        K = 512; N = 512; bx = idx & 15; by = idx >> 4;
        in = Wproj; out = wt + WTP;
    } else {
        int idx = bid - 9472;              // 0..255: fea pad job, k-space 512
        K = 512; N = 512; bx = idx & 15; by = idx >> 4;
        out = wt + WTF;
        in = (by < 12) ? nullptr : (Wfea - 384 * 512);   // k>=384 reads Wfea[k-384]
    }
    __shared__ float t[32][33];
    int k0 = by * 32, n0 = bx * 32;
    int tx = threadIdx.x, ty = threadIdx.y;
#pragma unroll
    for (int rr2 = 0; rr2 < 4; rr2++)
        t[ty + rr2 * 8][tx] = in ? in[(size_t)(k0 + ty + rr2 * 8) * N + n0 + tx] : 0.f;
    __syncthreads();
#pragma unroll
    for (int rr2 = 0; rr2 < 4; rr2++)
        out[(size_t)(n0 + ty + rr2 * 8) * K + k0 + tx] = __float2half(t[tx][ty + rr2 * 8]);
}

// ====== combined small packs: ktf | bqkv | btail | xcat =====================
__global__ void pack_misc(const float* __restrict__ kern,
                          const float* __restrict__ bq, const float* __restrict__ bk,
                          const float* __restrict__ bv,
                          const float* __restrict__ bproj, const float* __restrict__ bfea,
                          const float* __restrict__ x,
                          __half* __restrict__ kt, float* __restrict__ bdst,
                          float* __restrict__ btail, __half* __restrict__ xc)
{
    int bid = blockIdx.x, tidx = threadIdx.x;
    if (bid < 512) {
        int d = bid;
        kt[(size_t)d * 128 + tidx] =
            __float2half((tidx < Cn * 3) ? kern[(size_t)d * (Cn * 3) + tidx] : 0.f);
    } else if (bid < 524) {
        int j = bid - 512;
        int l = j >> 2, i = (j & 3) * 128 + tidx;
        bdst[l * 1536 + i]        = bq[l * 512 + i];
        bdst[l * 1536 + 512 + i]  = bk[l * 512 + i];
        bdst[l * 1536 + 1024 + i] = bv[l * 512 + i];
    } else if (bid < 532) {
        int i = (bid - 524) * 128 + tidx;    // 0..1023
        btail[i] = (i < 512) ? bproj[i] : bfea[i - 512];
    } else {
        int bl = bid - 532;
        int b = bl >> 9, l = bl & 511;
        float val = 0.f;
        if (tidx < Cn * 3) {
            int c = tidx / 3, t = tidx - c * 3;
            int ls = (l - 1 + t + Ln) & (Ln - 1);
            val = x[((size_t)b * Ln + ls) * Cn + c];
        }
        xc[(size_t)bl * 128 + tidx] = __float2half(val);
    }
}

// ===== layernorm (two-input, 128 thr x float4) =====
__global__ void add_ln512(const float* __restrict__ a, const float* __restrict__ b,
                          const float* __restrict__ g, const float* __restrict__ be,
                          float* __restrict__ o, __half* __restrict__ o16,
                          float* __restrict__ res) {
    int row = blockIdx.x, t = threadIdx.x;        // 128 threads
    size_t base = (size_t)row * Dn;
    float4 v = *(const float4*)(a + base + t * 4);
    if (b) {
        float4 vb = *(const float4*)(b + base + t * 4);
        v.x += vb.x; v.y += vb.y; v.z += vb.z; v.w += vb.w;
    }
    float s = v.x + v.y + v.z + v.w;
#pragma unroll
    for (int oo = 16; oo > 0; oo >>= 1) s += __shfl_xor_sync(0xFFFFFFFFu, s, oo);
    __shared__ float s1[4], s2[4];
    if ((t & 31) == 0) s1[t >> 5] = s;
    __syncthreads();
    float mean = (s1[0] + s1[1] + s1[2] + s1[3]) * (1.0f / Dn);
    float d0 = v.x - mean, d1 = v.y - mean, d2 = v.z - mean, d3 = v.w - mean;
    float q2 = d0 * d0 + d1 * d1 + d2 * d2 + d3 * d3;
#pragma unroll
    for (int oo = 16; oo > 0; oo >>= 1) q2 += __shfl_xor_sync(0xFFFFFFFFu, q2, oo);
    if ((t & 31) == 0) s2[t >> 5] = q2;
    __syncthreads();
    float var = (s2[0] + s2[1] + s2[2] + s2[3]) * (1.0f / Dn);
    float rr = rsqrtf(var + 1e-5f);
    float4 gg = *(const float4*)(g + t * 4);
    float4 bb = *(const float4*)(be + t * 4);
    float o0 = d0 * rr * gg.x + bb.x;
    float o1 = d1 * rr * gg.y + bb.y;
    float o2 = d2 * rr * gg.z + bb.z;
    float o3 = d3 * rr * gg.w + bb.w;
    if (o) {
        float4 ov = {o0, o1, o2, o3};
        *(float4*)(o + base + t * 4) = ov;
    }
    if (o16) {
        *(__half2*)(o16 + base + t * 4)     = __floats2half2_rn(o0, o1);
        *(__half2*)(o16 + base + t * 4 + 2) = __floats2half2_rn(o2, o3);
    }
    if (res && t < 96) {
        float4 rv = {o0, o1, o2, o3};
        *(float4*)(res + (size_t)row * 384 + t * 4) = rv;
    }
}

// ================= launcher =================
extern "C" void kernel_launch(void* const* d_in, const int* in_sizes, int n_in,
                              void* d_out, int out_size)
{
    const float* x     = (const float*)d_in[0];
    const float* embk  = (const float*)d_in[1];
    const float* Wq    = (const float*)d_in[2];
    const float* bq    = (const float*)d_in[3];
    const float* Wk    = (const float*)d_in[4];
    const float* bk    = (const float*)d_in[5];
    const float* Wv    = (const float*)d_in[6];
    const float* bv    = (const float*)d_in[7];
    // d_in[8], d_in[9]: Wsig/bsig are dead code in the reference
    const float* Wo    = (const float*)d_in[10];
    const float* bo    = (const float*)d_in[11];
    const float* W1    = (const float*)d_in[12];
    const float* b1    = (const float*)d_in[13];
    const float* W2    = (const float*)d_in[14];
    const float* b2    = (const float*)d_in[15];
    const float* n1g   = (const float*)d_in[16];
    const float* n1b   = (const float*)d_in[17];
    const float* n2g   = (const float*)d_in[18];
    const float* n2b   = (const float*)d_in[19];
    const float* nfg   = (const float*)d_in[20];
    const float* nfb   = (const float*)d_in[21];
    const float* Wproj = (const float*)d_in[22];
    const float* bproj = (const float*)d_in[23];
    const float* Wfea  = (const float*)d_in[24];
    const float* bfea  = (const float*)d_in[25];
    float* out = (float*)d_out;

    float *h, *x1, *tmp, *bqkv, *btail;
    __half *h16,*x1h,*enc16,*qkv,*attnv,*ff1,*xcat,*wt;
    cudaGetSymbolAddress((void**)&h,     g_h);
    cudaGetSymbolAddress((void**)&x1,    g_x1);
    cudaGetSymbolAddress((void**)&tmp,   g_tmp);
    cudaGetSymbolAddress((void**)&bqkv,  g_bqkv);
    cudaGetSymbolAddress((void**)&btail, g_btail);
    cudaGetSymbolAddress((void**)&h16,   g_h16);
    cudaGetSymbolAddress((void**)&x1h,   g_x1h);
    cudaGetSymbolAddress((void**)&enc16, g_enc16);
    cudaGetSymbolAddress((void**)&qkv,   g_qkv);
    cudaGetSymbolAddress((void**)&attnv, g_attnv);
    cudaGetSymbolAddress((void**)&ff1,   g_ff1);
    cudaGetSymbolAddress((void**)&xcat,  g_xcat);
    cudaGetSymbolAddress((void**)&wt,    g_wt);

    // outputs: fea_t | enc_res(384) | rec_temp(512) | emb(512)
    const size_t OFF_FEA = 0;
    const size_t OFF_RES = (size_t)Mn * Dn;
    const size_t OFF_REC = OFF_RES + (size_t)Mn * 384;
    const size_t OFF_EMB = OFF_REC + (size_t)Mn * Dn;
    float* emb = out + OFF_EMB;

    const int SM128 = 3 * (128 + 128) * 72 * 2;   // 110592 B (3 stages, K64 chunks)
    cudaFuncSetAttribute((const void*)gemm_mma<128,2>, cudaFuncAttributeMaxDynamicSharedMemorySize, SM128);
    cudaFuncSetAttribute((const void*)gemm_mma<128,8>, cudaFuncAttributeMaxDynamicSharedMemorySize, SM128);
    cudaFuncSetAttribute((const void*)gemm_mma<128,0>, cudaFuncAttributeMaxDynamicSharedMemorySize, SM128);
    cudaFuncSetAttribute((const void*)flash_attn, cudaFuncAttributeMaxDynamicSharedMemorySize, FL2_SMEM);

    // ---- preprocessing ----
    transpose_all<<<9728, dim3(32, 8)>>>(Wq, Wk, Wv, Wo, W1, W2, Wproj, Wfea, wt);
    pack_misc<<<532 + Mn, 128>>>(embk, bq, bk, bv, bproj, bfea, x,
                                 wt + KTF, bqkv, btail, xcat);

    // conv: K=128 -> NC=2 (unrolled)
    gemm_mma<128,2><<<dim3(4, 64), 256, SM128>>>(xcat, 128, wt + KTF, 128, nullptr,
                                                 emb, h16, Dn, 128, 0, nullptr);

    for (int l = 0; l < NLn; l++) {
        const float* hin = (l == 0) ? emb : h;
        size_t o512 = (size_t)l * Dn * Dn, o1 = (size_t)l * Dn * DFFn;
        gemm_mma<128,8><<<dim3(12, 64), 256, SM128>>>(h16, Dn, wt + WQKV(l), Dn,
                                                      bqkv + l * 1536, nullptr, qkv,
                                                      1536, Dn, 0, nullptr);
        flash_attn<<<dim3(BHn, 8), 256, FL2_SMEM>>>(qkv, attnv);
        gemm_mma<128,8><<<dim3(4, 64), 256, SM128>>>(attnv, Dn, wt + WTO + o512, Dn,
                                                     bo + l * Dn, tmp, nullptr,
                                                     Dn, Dn, 0, nullptr);
        add_ln512<<<Mn, 128>>>(hin, tmp, n1g + l * Dn, n1b + l * Dn, x1, x1h, nullptr);
        gemm_mma<128,8><<<dim3(16, 64), 256, SM128>>>(x1h, Dn, wt + WT1 + o1, Dn,
                                                      b1 + l * DFFn, nullptr, ff1,
                                                      DFFn, Dn, 1, nullptr);
        gemm_mma<128,0><<<dim3(4, 64), 256, SM128>>>(ff1, DFFn, wt + WT2 + o1, DFFn,
                                                     b2 + l * Dn, tmp, nullptr,
                                                     Dn, DFFn, 0, nullptr);
        add_ln512<<<Mn, 128>>>(x1, tmp, n2g + l * Dn, n2b + l * Dn, h, h16, nullptr);
    }

    add_ln512<<<Mn, 128>>>(h, nullptr, nfg, nfb, nullptr, enc16, out + OFF_RES);

    // merged tail: N=1024 (proj cols 0..511 -> rec_temp, fea cols 512..1023 -> fea_t)
    gemm_mma<128,8><<<dim3(8, 64), 256, SM128>>>(enc16, Dn, wt + WTP, Dn,
                                                 btail, out + OFF_REC, nullptr,
                                                 Dn, Dn, 0, out + OFF_FEA);
}